// round 5
// baseline (speedup 1.0000x reference)
#include <cuda_runtime.h>

#define BB   8
#define NN   128
#define COOR 3
#define FF   128
#define FILT 128

// Scratch: A' = x @ w1 + bv  and  C = x @ w2, each [B, N, COOR, FILT]
__device__ float g_A[BB * NN * COOR * FILT];
__device__ float g_C[BB * NN * COOR * FILT];

// ---- packed f32x2 helpers (phase 1 only) ----------------------------------
typedef unsigned long long ull;

union F4U {
    float4 f4;
    ull    u[2];
};

__device__ __forceinline__ ull fma2(ull a, ull b, ull c) {
    ull r;
    asm("fma.rn.f32x2 %0, %1, %2, %3;" : "=l"(r) : "l"(a), "l"(b), "l"(c));
    return r;
}
__device__ __forceinline__ ull pack2(float lo, float hi) {
    ull r;
    asm("mov.b64 %0, {%1, %2};" : "=l"(r) : "r"(__float_as_uint(lo)), "r"(__float_as_uint(hi)));
    return r;
}

// ---------------------------------------------------------------------------
// Phase 1: tiny GEMM [3072, 128] @ [128, 256]  ->  g_A (with +bv), g_C
// ONE warp per block, WR=4 rows per warp, 768 blocks (5.2 warps/SM, 6:5
// wave balance). Each lane owns a k-quad. Per f-iter: 2 LDG.128 (8 L1
// wavefronts) vs 16 fma2 (32 fma-pipe cyc) -> FMA-bound, and the w loads
// are prefetched TWO iterations ahead (64cyc span > 39cyc L1 latency).
// ---------------------------------------------------------------------------
__global__ __launch_bounds__(32) void phase1_kernel(
    const float* __restrict__ x,   // [3072, 128]
    const float* __restrict__ w,   // [256, 128]
    const float* __restrict__ bv)  // [128]
{
    constexpr int WR = 4;                 // rows per warp/block
    const int r0   = blockIdx.x * WR;     // 768 blocks
    const int lane = threadIdx.x;
    const int k    = lane * 4;

    __shared__ float xs[WR][FF];          // 2 KB

    {
        const float4* xin = reinterpret_cast<const float4*>(x + (size_t)r0 * FF);
        float4* xs4 = reinterpret_cast<float4*>(&xs[0][0]);
        #pragma unroll
        for (int t = lane; t < WR * FF / 4; t += 32) xs4[t] = xin[t];
    }
    __syncwarp();

    ull acc[WR][2][2];   // [row][A/C][pair]
    {
        F4U bvq;
        bvq.f4 = *reinterpret_cast<const float4*>(bv + k);
        #pragma unroll
        for (int r = 0; r < WR; r++) {
            acc[r][0][0] = bvq.u[0];  acc[r][0][1] = bvq.u[1];
            acc[r][1][0] = 0ull;      acc[r][1][1] = 0ull;
        }
    }

    const float4* w1p = reinterpret_cast<const float4*>(w) + lane;
    const float4* w2p = reinterpret_cast<const float4*>(w + (size_t)FF * FILT) + lane;

    // Depth-2 software pipeline on the w loads.
    F4U W1a, W2a, W1b, W2b;
    W1a.f4 = w1p[0];
    W2a.f4 = w2p[0];
    W1b.f4 = w1p[FILT / 4];
    W2b.f4 = w2p[FILT / 4];

    #pragma unroll 2
    for (int f = 0; f < FF; f++) {
        F4U P1, P2;
        if (f + 2 < FF) {
            P1.f4 = w1p[(f + 2) * (FILT / 4)];
            P2.f4 = w2p[(f + 2) * (FILT / 4)];
        }
        #pragma unroll
        for (int r = 0; r < WR; r++) {
            const float xv = xs[r][f];            // smem broadcast
            const ull xp = pack2(xv, xv);
            acc[r][0][0] = fma2(xp, W1a.u[0], acc[r][0][0]);
            acc[r][0][1] = fma2(xp, W1a.u[1], acc[r][0][1]);
            acc[r][1][0] = fma2(xp, W2a.u[0], acc[r][1][0]);
            acc[r][1][1] = fma2(xp, W2a.u[1], acc[r][1][1]);
        }
        W1a = W1b; W2a = W2b;
        W1b = P1;  W2b = P2;
    }

    #pragma unroll
    for (int r = 0; r < WR; r++) {
        const size_t row = (size_t)(r0 + r);
        F4U oa; oa.u[0] = acc[r][0][0]; oa.u[1] = acc[r][0][1];
        F4U oc; oc.u[0] = acc[r][1][0]; oc.u[1] = acc[r][1][1];
        *reinterpret_cast<float4*>(&g_A[row * FILT + k]) = oa.f4;
        *reinterpret_cast<float4*>(&g_C[row * FILT + k]) = oc.f4;
    }
}

// ---------------------------------------------------------------------------
// Phase 2: out[b,i,j,k] = sum_c (A'[b,i,c,k] + C[b,j,c,k]) * d[b,i,j,c]
// Grid (32, JS=2, 8) = 512 blocks; block (32,8): tx = k-quad, ty strides j
// within this block's 64-j half. TI=4 i-rows; A' in registers; distances
// padded to float4 in smem. __launch_bounds__(256,3) caps regs (~85) so 3
// blocks co-reside per SM (24 warps/SM) to hide the C-load L2 latency.
// ---------------------------------------------------------------------------
__global__ __launch_bounds__(256, 3) void phase2_kernel(
    const float* __restrict__ dist,  // [B, N, N, COOR]
    float* __restrict__ out)         // [B, N, N, FILT]
{
    constexpr int TI = 4;
    constexpr int JS = 2;
    constexpr int JT = NN / JS;      // 64

    const int b  = blockIdx.z;
    const int i0 = blockIdx.x * TI;
    const int j0 = blockIdx.y * JT;
    const int tx = threadIdx.x;      // 0..31
    const int ty = threadIdx.y;      // 0..7
    const int tid = ty * 32 + tx;

    __shared__ float4 sd4[TI * JT];  // padded (d0,d1,d2,_) per (i,jl): 4 KB

    // Load + pad distances slice d[b, i0:i0+4, j0:j0+64, :].
    {
        const float* dbase = dist + ((size_t)(b * NN + i0) * NN + j0) * COOR;
        #pragma unroll
        for (int t = tid; t < TI * JT; t += 256) {
            const int i  = t / JT;
            const int jl = t % JT;
            const float* p = dbase + (size_t)i * NN * COOR + jl * COOR;
            sd4[t] = make_float4(p[0], p[1], p[2], 0.0f);
        }
    }

    // A' tile into registers: 4 i x 3 c x float4 = 48 regs.
    float4 Ar[TI][COOR];
    {
        const float4* A4 = reinterpret_cast<const float4*>(g_A);
        #pragma unroll
        for (int i = 0; i < TI; i++)
            #pragma unroll
            for (int c = 0; c < COOR; c++)
                Ar[i][c] = A4[((size_t)(b * NN + i0 + i) * COOR + c) * (FILT / 4) + tx];
    }
    __syncthreads();

    const float4* C4 = reinterpret_cast<const float4*>(g_C) +
                       (size_t)b * NN * COOR * (FILT / 4) + tx;
    float4* out4 = reinterpret_cast<float4*>(out) +
                   ((size_t)(b * NN + i0) * NN + j0) * (FILT / 4) + tx;

    #pragma unroll 2
    for (int it = 0; it < JT / 8; it++) {
        const int jl = ty + it * 8;        // local j in [0, JT)
        const int j  = j0 + jl;

        const size_t cb = (size_t)j * COOR * (FILT / 4);
        const float4 c0 = C4[cb + 0 * (FILT / 4)];
        const float4 c1 = C4[cb + 1 * (FILT / 4)];
        const float4 c2 = C4[cb + 2 * (FILT / 4)];

        #pragma unroll
        for (int i = 0; i < TI; i++) {
            const float4 dv = sd4[i * JT + jl];   // one LDS.128 broadcast
            const float d0 = dv.x, d1 = dv.y, d2 = dv.z;

            float4 o;
            o.x = fmaf(Ar[i][0].x + c0.x, d0,
                  fmaf(Ar[i][1].x + c1.x, d1, (Ar[i][2].x + c2.x) * d2));
            o.y = fmaf(Ar[i][0].y + c0.y, d0,
                  fmaf(Ar[i][1].y + c1.y, d1, (Ar[i][2].y + c2.y) * d2));
            o.z = fmaf(Ar[i][0].z + c0.z, d0,
                  fmaf(Ar[i][1].z + c1.z, d1, (Ar[i][2].z + c2.z) * d2));
            o.w = fmaf(Ar[i][0].w + c0.w, d0,
                  fmaf(Ar[i][1].w + c1.w, d1, (Ar[i][2].w + c2.w) * d2));

            out4[((size_t)i * NN + jl) * (FILT / 4)] = o;
        }
    }
}

extern "C" void kernel_launch(void* const* d_in, const int* in_sizes, int n_in,
                              void* d_out, int out_size)
{
    const float* x    = (const float*)d_in[0];  // vector_features [8,128,3,128]
    const float* dist = (const float*)d_in[1];  // distances       [8,128,128,3]
    const float* w    = (const float*)d_in[2];  // w_vs            [256,128]
    const float* bv   = (const float*)d_in[3];  // b_vs            [128]
    float* out = (float*)d_out;                 // [8,128,128,128]

    (void)in_sizes; (void)n_in; (void)out_size;

    phase1_kernel<<<(BB * NN * COOR) / 4, 32>>>(x, w, bv);
    phase2_kernel<<<dim3(NN / 4, 2, BB), dim3(32, 8)>>>(dist, out);
}

// round 6
// speedup vs baseline: 1.2143x; 1.2143x over previous
#include <cuda_runtime.h>

#define BB   8
#define NN   128
#define COOR 3
#define FF   128
#define FILT 128

// Scratch: A' = x @ w1 + bv  and  C = x @ w2, each [B, N, COOR, FILT]
__device__ float g_A[BB * NN * COOR * FILT];
__device__ float g_C[BB * NN * COOR * FILT];

// ---- packed f32x2 helpers --------------------------------------------------
typedef unsigned long long ull;

union F2U {
    float2 f2;
    ull    u;
};

__device__ __forceinline__ ull fma2(ull a, ull b, ull c) {
    ull r;
    asm("fma.rn.f32x2 %0, %1, %2, %3;" : "=l"(r) : "l"(a), "l"(b), "l"(c));
    return r;
}
__device__ __forceinline__ ull pack2(float lo, float hi) {
    ull r;
    asm("mov.b64 %0, {%1, %2};" : "=l"(r) : "r"(__float_as_uint(lo)), "r"(__float_as_uint(hi)));
    return r;
}

// ---------------------------------------------------------------------------
// Phase 1: tiny GEMM [3072, 128] @ [128, 256]  ->  g_A (with +bv), g_C
// 2-D tiled to kill w-load redundancy: grid (192 row-tiles, 2 k-halves).
// Block = 128 thr (4 warps); each warp owns 4 rows x 64 k (lane = k-pair).
// Per warp-iter: 2x LDG.64 (512 B w) + 4 LDS broadcasts + 8 fma2.
// Chip w-traffic: 384 blocks x 64 KB = 24.5 MB (was 196 MB at WR=2 full-k).
// Depth-2 prefetch on w covers the ~39cyc L1 latency.
// ---------------------------------------------------------------------------
__global__ __launch_bounds__(128) void phase1_kernel(
    const float* __restrict__ x,   // [3072, 128]
    const float* __restrict__ w,   // [256, 128]
    const float* __restrict__ bv)  // [128]
{
    constexpr int RT = 16;               // rows per block
    constexpr int KH = 64;               // k per block (half)
    const int r0   = blockIdx.x * RT;
    const int kh   = blockIdx.y * KH;
    const int warp = threadIdx.x >> 5;   // 0..3
    const int lane = threadIdx.x & 31;
    const int k    = kh + lane * 2;      // this thread's k-pair
    const int wr   = warp * 4;           // first of this warp's 4 rows

    __shared__ float xs[RT][FF];         // 8 KB

    {
        const float4* xin = reinterpret_cast<const float4*>(x + (size_t)r0 * FF);
        float4* xs4 = reinterpret_cast<float4*>(&xs[0][0]);
        #pragma unroll
        for (int t = threadIdx.x; t < RT * FF / 4; t += 128) xs4[t] = xin[t];
    }
    __syncthreads();

    ull acc[4][2];   // [row][A/C]
    {
        const float2 b2 = *reinterpret_cast<const float2*>(bv + k);
        const ull bp = pack2(b2.x, b2.y);
        #pragma unroll
        for (int r = 0; r < 4; r++) { acc[r][0] = bp; acc[r][1] = 0ull; }
    }

    const float* w1base = w + kh + lane * 2;
    const float* w2base = w + (size_t)FF * FILT + kh + lane * 2;

    // Depth-2 software pipeline on the w loads.
    F2U W1a, W2a, W1b, W2b;
    W1a.f2 = *reinterpret_cast<const float2*>(w1base);
    W2a.f2 = *reinterpret_cast<const float2*>(w2base);
    W1b.f2 = *reinterpret_cast<const float2*>(w1base + FILT);
    W2b.f2 = *reinterpret_cast<const float2*>(w2base + FILT);

    #pragma unroll 4
    for (int f = 0; f < FF; f++) {
        F2U P1, P2;
        if (f + 2 < FF) {
            P1.f2 = *reinterpret_cast<const float2*>(w1base + (size_t)(f + 2) * FILT);
            P2.f2 = *reinterpret_cast<const float2*>(w2base + (size_t)(f + 2) * FILT);
        }
        #pragma unroll
        for (int r = 0; r < 4; r++) {
            const float xv = xs[wr + r][f];      // smem broadcast
            const ull xp = pack2(xv, xv);
            acc[r][0] = fma2(xp, W1a.u, acc[r][0]);
            acc[r][1] = fma2(xp, W2a.u, acc[r][1]);
        }
        W1a = W1b; W2a = W2b;
        W1b = P1;  W2b = P2;
    }

    #pragma unroll
    for (int r = 0; r < 4; r++) {
        const size_t row = (size_t)(r0 + wr + r);
        F2U oa; oa.u = acc[r][0];
        F2U oc; oc.u = acc[r][1];
        *reinterpret_cast<float2*>(&g_A[row * FILT + k]) = oa.f2;
        *reinterpret_cast<float2*>(&g_C[row * FILT + k]) = oc.f2;
    }
}

// ---------------------------------------------------------------------------
// Phase 2 (R4 config — best known: 16.35us): 256 blocks, single wave.
// out[b,i,j,k] = sum_c (A'[b,i,c,k] + C[b,j,c,k]) * d[b,i,j,c]
// Block (32,8): tx = k-quad, ty strides j over all 128. TI=4 i-rows.
// A' in registers; distances padded to float4 in smem (1 LDS.128/(i,j));
// C loads software-pipelined one j-iteration ahead.
// ---------------------------------------------------------------------------
__global__ __launch_bounds__(256) void phase2_kernel(
    const float* __restrict__ dist,  // [B, N, N, COOR]
    float* __restrict__ out)         // [B, N, N, FILT]
{
    constexpr int TI = 4;
    const int b  = blockIdx.y;
    const int i0 = blockIdx.x * TI;
    const int tx = threadIdx.x;   // 0..31
    const int ty = threadIdx.y;   // 0..7
    const int tid = ty * 32 + tx;

    __shared__ float4 sd4[TI * NN];   // 8 KB

    {
        const float* dbase = dist + (size_t)(b * NN + i0) * NN * COOR;
        #pragma unroll
        for (int t = tid; t < TI * NN; t += 256) {
            const int e = t * COOR;
            sd4[t] = make_float4(dbase[e], dbase[e + 1], dbase[e + 2], 0.0f);
        }
    }

    float4 Ar[TI][COOR];
    {
        const float4* A4 = reinterpret_cast<const float4*>(g_A);
        #pragma unroll
        for (int i = 0; i < TI; i++)
            #pragma unroll
            for (int c = 0; c < COOR; c++)
                Ar[i][c] = A4[((size_t)(b * NN + i0 + i) * COOR + c) * (FILT / 4) + tx];
    }
    __syncthreads();

    const float4* C4 = reinterpret_cast<const float4*>(g_C) +
                       (size_t)b * NN * COOR * (FILT / 4) + tx;
    float4* out4 = reinterpret_cast<float4*>(out) +
                   ((size_t)(b * NN + i0) * NN) * (FILT / 4) + tx;

    float4 c0 = C4[(size_t)ty * COOR * (FILT / 4) + 0 * (FILT / 4)];
    float4 c1 = C4[(size_t)ty * COOR * (FILT / 4) + 1 * (FILT / 4)];
    float4 c2 = C4[(size_t)ty * COOR * (FILT / 4) + 2 * (FILT / 4)];

    #pragma unroll
    for (int it = 0; it < NN / 8; it++) {
        const int j = ty + it * 8;

        float4 n0, n1, n2;
        if (it + 1 < NN / 8) {
            const size_t nb = (size_t)(j + 8) * COOR * (FILT / 4);
            n0 = C4[nb + 0 * (FILT / 4)];
            n1 = C4[nb + 1 * (FILT / 4)];
            n2 = C4[nb + 2 * (FILT / 4)];
        }

        #pragma unroll
        for (int i = 0; i < TI; i++) {
            const float4 dv = sd4[i * NN + j];   // one LDS.128 broadcast
            const float d0 = dv.x, d1 = dv.y, d2 = dv.z;

            float4 o;
            o.x = fmaf(Ar[i][0].x + c0.x, d0,
                  fmaf(Ar[i][1].x + c1.x, d1, (Ar[i][2].x + c2.x) * d2));
            o.y = fmaf(Ar[i][0].y + c0.y, d0,
                  fmaf(Ar[i][1].y + c1.y, d1, (Ar[i][2].y + c2.y) * d2));
            o.z = fmaf(Ar[i][0].z + c0.z, d0,
                  fmaf(Ar[i][1].z + c1.z, d1, (Ar[i][2].z + c2.z) * d2));
            o.w = fmaf(Ar[i][0].w + c0.w, d0,
                  fmaf(Ar[i][1].w + c1.w, d1, (Ar[i][2].w + c2.w) * d2));

            out4[((size_t)i * NN + j) * (FILT / 4)] = o;
        }

        c0 = n0; c1 = n1; c2 = n2;
    }
}

extern "C" void kernel_launch(void* const* d_in, const int* in_sizes, int n_in,
                              void* d_out, int out_size)
{
    const float* x    = (const float*)d_in[0];  // vector_features [8,128,3,128]
    const float* dist = (const float*)d_in[1];  // distances       [8,128,128,3]
    const float* w    = (const float*)d_in[2];  // w_vs            [256,128]
    const float* bv   = (const float*)d_in[3];  // b_vs            [128]
    float* out = (float*)d_out;                 // [8,128,128,128]

    (void)in_sizes; (void)n_in; (void)out_size;

    phase1_kernel<<<dim3((BB * NN * COOR) / 16, 2), 128>>>(x, w, bv);
    phase2_kernel<<<dim3(NN / 4, BB), dim3(32, 8)>>>(dist, out);
    // Deliberate idempotent re-run of phase1: makes the launch pattern
    // period-3 so ncu's "-s 5 -c 1" (6th launch) finally profiles phase1.
    // Rewrites g_A/g_C with identical values -> deterministic.
    phase1_kernel<<<dim3((BB * NN * COOR) / 16, 2), 128>>>(x, w, bv);
}

// round 7
// speedup vs baseline: 1.9839x; 1.6338x over previous
#include <cuda_runtime.h>

#define BB   8
#define NN   128
#define COOR 3
#define FF   128
#define FILT 128

// Scratch: A' = x @ w1 + bv  and  C = x @ w2, each [B, N, COOR, FILT]
__device__ float g_A[BB * NN * COOR * FILT];
__device__ float g_C[BB * NN * COOR * FILT];

// ---- packed f32x2 helpers --------------------------------------------------
typedef unsigned long long ull;

union F2U {
    float2 f2;
    ull    u;
};

__device__ __forceinline__ ull fma2(ull a, ull b, ull c) {
    ull r;
    asm("fma.rn.f32x2 %0, %1, %2, %3;" : "=l"(r) : "l"(a), "l"(b), "l"(c));
    return r;
}
__device__ __forceinline__ ull pack2(float lo, float hi) {
    ull r;
    asm("mov.b64 %0, {%1, %2};" : "=l"(r) : "r"(__float_as_uint(lo)), "r"(__float_as_uint(hi)));
    return r;
}

// ---------------------------------------------------------------------------
// Phase 1: tiny GEMM [3072, 128] @ [128, 256]  ->  g_A (with +bv), g_C
// Latency-first design (R6 profile showed ALL pipes idle, warps stalled on
// the w scoreboard: L1 is flushed per launch so w comes from L2 @~250cyc):
//   * 2 rows/warp, 8 rows/block, grid (384, 2) = 768 blocks
//     -> 20.8 warps/SM (was 10.4), occ ~32%
//   * DEPTH=8 rotating w-prefetch pipeline, statically indexed:
//     wait-arm spans ~8 iters x ~50cyc wall >= 262cyc L2-far latency.
// Issue-slot floor: 20.8w x 128f x ~10instr / 4 SMSP ~ 6.7Kcyc ~ 3.3us.
// ---------------------------------------------------------------------------
__global__ __launch_bounds__(128) void phase1_kernel(
    const float* __restrict__ x,   // [3072, 128]
    const float* __restrict__ w,   // [256, 128]
    const float* __restrict__ bv)  // [128]
{
    constexpr int RT    = 8;             // rows per block
    constexpr int DEPTH = 8;             // w-prefetch pipeline depth
    const int r0   = blockIdx.x * RT;
    const int kh   = blockIdx.y * 64;    // k half
    const int warp = threadIdx.x >> 5;   // 0..3
    const int lane = threadIdx.x & 31;
    const int k    = kh + lane * 2;      // this thread's k-pair
    const int wr   = warp * 2;           // first of this warp's 2 rows

    __shared__ float xs[RT][FF];         // 4 KB

    {
        const float4* xin = reinterpret_cast<const float4*>(x + (size_t)r0 * FF);
        float4* xs4 = reinterpret_cast<float4*>(&xs[0][0]);
        #pragma unroll
        for (int t = threadIdx.x; t < RT * FF / 4; t += 128) xs4[t] = xin[t];
    }
    __syncthreads();

    ull acc[2][2];   // [row][A/C]
    {
        const float2 b2 = *reinterpret_cast<const float2*>(bv + k);
        const ull bp = pack2(b2.x, b2.y);
        acc[0][0] = bp; acc[0][1] = 0ull;
        acc[1][0] = bp; acc[1][1] = 0ull;
    }

    const float* w1base = w + k;
    const float* w2base = w + (size_t)FF * FILT + k;

    // Prime the depth-8 rotating pipeline.
    F2U W1[DEPTH], W2[DEPTH];
    #pragma unroll
    for (int d = 0; d < DEPTH; d++) {
        W1[d].f2 = *reinterpret_cast<const float2*>(w1base + (size_t)d * FILT);
        W2[d].f2 = *reinterpret_cast<const float2*>(w2base + (size_t)d * FILT);
    }

    #pragma unroll 8   // = DEPTH, so f % DEPTH is a compile-time slot index
    for (int f = 0; f < FF; f++) {
        const int slot = f % DEPTH;

        const float xv0 = xs[wr + 0][f];     // smem broadcast
        const float xv1 = xs[wr + 1][f];
        const ull xp0 = pack2(xv0, xv0);
        const ull xp1 = pack2(xv1, xv1);

        const ull w1v = W1[slot].u;
        const ull w2v = W2[slot].u;

        acc[0][0] = fma2(xp0, w1v, acc[0][0]);
        acc[0][1] = fma2(xp0, w2v, acc[0][1]);
        acc[1][0] = fma2(xp1, w1v, acc[1][0]);
        acc[1][1] = fma2(xp1, w2v, acc[1][1]);

        // Refill this slot for iteration f + DEPTH.
        if (f + DEPTH < FF) {
            W1[slot].f2 = *reinterpret_cast<const float2*>(w1base + (size_t)(f + DEPTH) * FILT);
            W2[slot].f2 = *reinterpret_cast<const float2*>(w2base + (size_t)(f + DEPTH) * FILT);
        }
    }

    #pragma unroll
    for (int r = 0; r < 2; r++) {
        const size_t row = (size_t)(r0 + wr + r);
        F2U oa; oa.u = acc[r][0];
        F2U oc; oc.u = acc[r][1];
        *reinterpret_cast<float2*>(&g_A[row * FILT + k]) = oa.f2;
        *reinterpret_cast<float2*>(&g_C[row * FILT + k]) = oc.f2;
    }
}

// ---------------------------------------------------------------------------
// Phase 2 (best known config, 16.35us): 256 blocks, single clean wave.
// out[b,i,j,k] = sum_c (A'[b,i,c,k] + C[b,j,c,k]) * d[b,i,j,c]
// Block (32,8): tx = k-quad, ty strides j over all 128. TI=4 i-rows.
// A' in registers; distances padded to float4 in smem (1 LDS.128/(i,j));
// C loads software-pipelined one j-iteration ahead.
// ---------------------------------------------------------------------------
__global__ __launch_bounds__(256) void phase2_kernel(
    const float* __restrict__ dist,  // [B, N, N, COOR]
    float* __restrict__ out)         // [B, N, N, FILT]
{
    constexpr int TI = 4;
    const int b  = blockIdx.y;
    const int i0 = blockIdx.x * TI;
    const int tx = threadIdx.x;   // 0..31
    const int ty = threadIdx.y;   // 0..7
    const int tid = ty * 32 + tx;

    __shared__ float4 sd4[TI * NN];   // 8 KB

    {
        const float* dbase = dist + (size_t)(b * NN + i0) * NN * COOR;
        #pragma unroll
        for (int t = tid; t < TI * NN; t += 256) {
            const int e = t * COOR;
            sd4[t] = make_float4(dbase[e], dbase[e + 1], dbase[e + 2], 0.0f);
        }
    }

    float4 Ar[TI][COOR];
    {
        const float4* A4 = reinterpret_cast<const float4*>(g_A);
        #pragma unroll
        for (int i = 0; i < TI; i++)
            #pragma unroll
            for (int c = 0; c < COOR; c++)
                Ar[i][c] = A4[((size_t)(b * NN + i0 + i) * COOR + c) * (FILT / 4) + tx];
    }
    __syncthreads();

    const float4* C4 = reinterpret_cast<const float4*>(g_C) +
                       (size_t)b * NN * COOR * (FILT / 4) + tx;
    float4* out4 = reinterpret_cast<float4*>(out) +
                   ((size_t)(b * NN + i0) * NN) * (FILT / 4) + tx;

    float4 c0 = C4[(size_t)ty * COOR * (FILT / 4) + 0 * (FILT / 4)];
    float4 c1 = C4[(size_t)ty * COOR * (FILT / 4) + 1 * (FILT / 4)];
    float4 c2 = C4[(size_t)ty * COOR * (FILT / 4) + 2 * (FILT / 4)];

    #pragma unroll
    for (int it = 0; it < NN / 8; it++) {
        const int j = ty + it * 8;

        float4 n0, n1, n2;
        if (it + 1 < NN / 8) {
            const size_t nb = (size_t)(j + 8) * COOR * (FILT / 4);
            n0 = C4[nb + 0 * (FILT / 4)];
            n1 = C4[nb + 1 * (FILT / 4)];
            n2 = C4[nb + 2 * (FILT / 4)];
        }

        #pragma unroll
        for (int i = 0; i < TI; i++) {
            const float4 dv = sd4[i * NN + j];   // one LDS.128 broadcast
            const float d0 = dv.x, d1 = dv.y, d2 = dv.z;

            float4 o;
            o.x = fmaf(Ar[i][0].x + c0.x, d0,
                  fmaf(Ar[i][1].x + c1.x, d1, (Ar[i][2].x + c2.x) * d2));
            o.y = fmaf(Ar[i][0].y + c0.y, d0,
                  fmaf(Ar[i][1].y + c1.y, d1, (Ar[i][2].y + c2.y) * d2));
            o.z = fmaf(Ar[i][0].z + c0.z, d0,
                  fmaf(Ar[i][1].z + c1.z, d1, (Ar[i][2].z + c2.z) * d2));
            o.w = fmaf(Ar[i][0].w + c0.w, d0,
                  fmaf(Ar[i][1].w + c1.w, d1, (Ar[i][2].w + c2.w) * d2));

            out4[((size_t)i * NN + j) * (FILT / 4)] = o;
        }

        c0 = n0; c1 = n1; c2 = n2;
    }
}

extern "C" void kernel_launch(void* const* d_in, const int* in_sizes, int n_in,
                              void* d_out, int out_size)
{
    const float* x    = (const float*)d_in[0];  // vector_features [8,128,3,128]
    const float* dist = (const float*)d_in[1];  // distances       [8,128,128,3]
    const float* w    = (const float*)d_in[2];  // w_vs            [256,128]
    const float* bv   = (const float*)d_in[3];  // b_vs            [128]
    float* out = (float*)d_out;                 // [8,128,128,128]

    (void)in_sizes; (void)n_in; (void)out_size;

    phase1_kernel<<<dim3((BB * NN * COOR) / 8, 2), 128>>>(x, w, bv);
    phase2_kernel<<<dim3(NN / 4, BB), dim3(32, 8)>>>(dist, out);
}